// round 1
// baseline (speedup 1.0000x reference)
#include <cuda_runtime.h>

#define N_Q   9
#define DIM   512
#define C_CH  3
#define KW    3
#define LEN   2048
#define LOUT  2046
#define BATCH 8
#define OCH   8
#define WPB   8   // warps per block = batches

__global__ __launch_bounds__(256)
void qconv_kernel(const float* __restrict__ x,
                  const float* __restrict__ theta,
                  float* __restrict__ out)
{
    __shared__ float  perm[WPB][DIM];
    __shared__ float2 gcs[OCH][N_Q];

    const int tid  = threadIdx.x;
    const int warp = tid >> 5;
    const int lane = tid & 31;
    const int t    = blockIdx.x;   // window position 0..LOUT-1
    const int b    = warp;         // batch index

    // Per-block gate coefficient table: cos/sin(theta/2)
    if (tid < OCH * N_Q) {
        float s, c;
        sincosf(0.5f * theta[tid], &s, &c);
        gcs[tid / N_Q][tid % N_Q] = make_float2(c, s);
    }
    __syncthreads();

    // Window angles -> cos/sin(x/2). Qubit i = 3*channel + offset.
    float cx[N_Q], sx[N_Q];
#pragma unroll
    for (int i = 0; i < N_Q; ++i) {
        const int ch = i / KW, k = i % KW;
        const float xv = x[(b * C_CH + ch) * LEN + t + k];
        sincosf(0.5f * xv, &sx[i], &cx[i]);
    }

    // Product state. Index j = lane*16 + reg. Qubit q <-> bit (8-q):
    //   qubits 0..4 -> lane bits 4..0 ; qubits 5..8 -> reg bits 3..0.
    float lf = 1.0f;
#pragma unroll
    for (int i = 0; i < 5; ++i)
        lf *= ((lane >> (4 - i)) & 1) ? sx[i] : cx[i];

    float v[16];
    v[0] = lf;
#pragma unroll
    for (int bp = 0; bp < 4; ++bp) {       // reg bit bp <-> qubit 8-bp
        const int qi = 8 - bp;
        const int sz = 1 << bp;
#pragma unroll
        for (int u = 0; u < 8; ++u) {
            if (u < sz) {
                v[u + sz] = v[u] * sx[qi];
                v[u]      = v[u] * cx[qi];
            }
        }
    }

    // Unnormalized WHT: in-register stages (bits 0..3)
#pragma unroll
    for (int k = 0; k < 4; ++k) {
        const int mk = 1 << k;
#pragma unroll
        for (int r = 0; r < 16; ++r) {
            if (!(r & mk)) {
                const float a = v[r], bb = v[r | mk];
                v[r]      = a + bb;
                v[r | mk] = a - bb;
            }
        }
    }
    // Cross-lane stages (bits 4..8)
#pragma unroll
    for (int p = 0; p < 5; ++p) {
        const int lm = 1 << p;
        const float sgn = (lane & lm) ? -1.0f : 1.0f;
#pragma unroll
        for (int r = 0; r < 16; ++r) {
            const float o = __shfl_xor_sync(0xffffffffu, v[r], lm);
            v[r] = fmaf(sgn, v[r], o);
        }
    }

    // Scatter through the CNOT-ring permutation (replicates reference idx
    // construction exactly), with the 1/sqrt(512) normalization of E.
    const float scale = 0.044194173824159216f;
    float* sp = perm[warp];
#pragma unroll
    for (int r = 0; r < 16; ++r) {
        int id = (lane << 4) | r;
#pragma unroll
        for (int c = 0; c < N_Q - 1; ++c) {
            const int bit = (id >> (N_Q - 1 - c)) & 1;
            id ^= bit << (N_Q - 1 - (c + 1));
        }
        {   // last pair (n-1, 0)
            const int bit = id & 1;
            id ^= bit << (N_Q - 1);
        }
        sp[id] = v[r] * scale;
    }
    __syncwarp();

    float base[16];
#pragma unroll
    for (int r = 0; r < 16; ++r)
        base[r] = sp[(lane << 4) | r];

    // Channels: RY rotations on qubits 1..8 (qubit 0 provably drops out),
    // then result = sum_j z_j * z_{j ^ 0xFF}  (second E folded away).
    for (int o = 0; o < OCH; ++o) {
        float z[16];
#pragma unroll
        for (int r = 0; r < 16; ++r) z[r] = base[r];

        // Cross-lane rotations: index bits 7..4 -> qubits 1..4
#pragma unroll
        for (int p = 4; p < 8; ++p) {
            const float2 g  = gcs[o][8 - p];
            const int    lm = 1 << (p - 4);
            const float  ss = (lane & lm) ? g.y : -g.y;
#pragma unroll
            for (int r = 0; r < 16; ++r) {
                const float pv = __shfl_xor_sync(0xffffffffu, z[r], lm);
                z[r] = fmaf(ss, pv, g.x * z[r]);
            }
        }
        // In-register rotations: index bits 3..0 -> qubits 5..8
#pragma unroll
        for (int p = 0; p < 4; ++p) {
            const float2 g  = gcs[o][8 - p];
            const int    mk = 1 << p;
#pragma unroll
            for (int r = 0; r < 16; ++r) {
                if (!(r & mk)) {
                    const float a = z[r], bb = z[r | mk];
                    z[r]      = fmaf(-g.y, bb, g.x * a);
                    z[r | mk] = fmaf( g.y, a,  g.x * bb);
                }
            }
        }

        // Correlation: j ^ 0xFF  ->  reg ^ 0xF on lane ^ 0xF
        float acc = 0.0f;
#pragma unroll
        for (int r = 0; r < 16; ++r) {
            const float pv = __shfl_xor_sync(0xffffffffu, z[15 - r], 0x0F);
            acc = fmaf(z[r], pv, acc);
        }
#pragma unroll
        for (int off = 16; off > 0; off >>= 1)
            acc += __shfl_xor_sync(0xffffffffu, acc, off);

        if (lane == 0)
            out[(b * OCH + o) * LOUT + t] = acc;
    }
}

extern "C" void kernel_launch(void* const* d_in, const int* in_sizes, int n_in,
                              void* d_out, int out_size)
{
    const float* x_ptr  = nullptr;
    const float* th_ptr = nullptr;
    for (int i = 0; i < n_in; ++i) {
        if (in_sizes[i] == BATCH * C_CH * LEN) x_ptr  = (const float*)d_in[i];
        else if (in_sizes[i] == OCH * N_Q)     th_ptr = (const float*)d_in[i];
    }
    // fallback to documented order: x, entangle, theta
    if (!x_ptr)  x_ptr  = (const float*)d_in[0];
    if (!th_ptr) th_ptr = (const float*)d_in[n_in - 1];

    qconv_kernel<<<LOUT, 256>>>(x_ptr, th_ptr, (float*)d_out);
}

// round 2
// speedup vs baseline: 1.7015x; 1.7015x over previous
#include <cuda_runtime.h>

typedef unsigned long long u64;

#define N_Q   9
#define C_CH  3
#define LEN   2048
#define LOUT  2046
#define BATCH 8
#define OCH   8
#define WPB   8

// ---------- packed f32x2 helpers (ptxas won't auto-fuse these) ----------
__device__ __forceinline__ u64 pk2(float lo, float hi){
    u64 r; asm("mov.b64 %0, {%1, %2};" : "=l"(r) : "f"(lo), "f"(hi)); return r;
}
__device__ __forceinline__ float lo2(u64 v){
    float a; asm("{.reg .b32 h_; mov.b64 {%0, h_}, %1;}" : "=f"(a) : "l"(v)); return a;
}
__device__ __forceinline__ float hi2(u64 v){
    float a; asm("{.reg .b32 l_; mov.b64 {l_, %0}, %1;}" : "=f"(a) : "l"(v)); return a;
}
__device__ __forceinline__ u64 fma2(u64 a, u64 b, u64 c){
    u64 d; asm("fma.rn.f32x2 %0, %1, %2, %3;" : "=l"(d) : "l"(a), "l"(b), "l"(c)); return d;
}
__device__ __forceinline__ u64 mul2(u64 a, u64 b){
    u64 d; asm("mul.rn.f32x2 %0, %1, %2;" : "=l"(d) : "l"(a), "l"(b)); return d;
}
__device__ __forceinline__ u64 add2(u64 a, u64 b){
    u64 d; asm("add.rn.f32x2 %0, %1, %2;" : "=l"(d) : "l"(a), "l"(b)); return d;
}
__device__ __forceinline__ u64 swp2(u64 v){
    u64 r; asm("{.reg .b32 a_, b_; mov.b64 {a_, b_}, %1; mov.b64 %0, {b_, a_};}"
               : "=l"(r) : "l"(v)); return r;
}

// CNOT-ring permutation (replicates reference idx construction; linear over GF(2))
__device__ __forceinline__ int permref(int id){
#pragma unroll
    for (int c = 0; c < N_Q - 1; ++c){
        const int bit = (id >> (N_Q - 1 - c)) & 1;
        id ^= bit << (N_Q - 2 - c);
    }
    id ^= (id & 1) << (N_Q - 1);
    return id;
}

// Transpose within a warp: swap index bits 7..4 <-> 3..0 (bit 8 = lane bit 4 fixed).
// Stride-17 padding -> conflict-free writes and reads.
__device__ __forceinline__ void xpose(u64* V, float* S, int wbase, int rbase){
    __syncwarp();
#pragma unroll
    for (int p = 0; p < 8; ++p){
        S[wbase + 2*p]     = lo2(V[p]);
        S[wbase + 2*p + 1] = hi2(V[p]);
    }
    __syncwarp();
#pragma unroll
    for (int p = 0; p < 8; ++p)
        V[p] = pk2(S[rbase + 17*(2*p)], S[rbase + 17*(2*p + 1)]);
}

__global__ __launch_bounds__(256)
void qconv_kernel(const float* __restrict__ x,
                  const float* __restrict__ theta,
                  float* __restrict__ out)
{
    __shared__ float smx[WPB][544];      // per-warp transpose / perm buffer
    __shared__ u64   gtt[OCH][8];        // (tan phi, tan phi) packs, qubits 1..8
    __shared__ float gc2[OCH * 8];       // cos^2 phi per gate (temp)
    __shared__ float gK[OCH];            // (prod cos phi)^2 per channel

    const int tid  = threadIdx.x;
    const int warp = tid >> 5;
    const int lane = tid & 31;
    const int t    = blockIdx.x;         // window position
    const int b    = warp;               // batch

    // ---- gate prep: phi = pi/4 - theta/2 ; store tan-packs and cos^2 ----
    if (tid < OCH * 8){
        const int o = tid >> 3, qi = tid & 7;          // qubit = qi+1 (qubit 0 drops out)
        const float th  = theta[o * N_Q + qi + 1];
        const float phi = 0.78539816339744830962f - 0.5f * th;
        float s, c; sincosf(phi, &s, &c);
        const float tt = s / c;
        gtt[o][qi] = pk2(tt, tt);
        gc2[tid]   = c * c;
    }
    __syncthreads();
    if (tid < OCH){
        float k = 1.0f;
#pragma unroll
        for (int q = 0; q < 8; ++q) k *= gc2[tid * 8 + q];
        gK[tid] = k;
    }
    __syncthreads();

    // ---- window angles ----
    float cx[N_Q], sx[N_Q];
#pragma unroll
    for (int i = 0; i < N_Q; ++i){
        const int ch = i / 3, k = i % 3;
        sincosf(0.5f * x[(b * C_CH + ch) * LEN + t + k], &sx[i], &cx[i]);
    }

    // ---- product state, layout A: j = lane<<4 | r ; qubit q <-> bit 8-q ----
    // 1/sqrt(512) of E folded in here.
    float lf = 0.044194173824159220275f;
#pragma unroll
    for (int i = 0; i < 5; ++i)
        lf *= ((lane >> (4 - i)) & 1) ? sx[i] : cx[i];

    u64 V[8];
    V[0] = mul2(pk2(lf, lf), pk2(cx[8], sx[8]));       // reg bit0 = qubit 8
#pragma unroll
    for (int bp = 1; bp < 4; ++bp){                    // reg bits 1..3 = qubits 7,6,5
        const int qi = 8 - bp;
        const u64 cb = pk2(cx[qi], cx[qi]);
        const u64 sb = pk2(sx[qi], sx[qi]);
        const int sz = 1 << (bp - 1);
#pragma unroll
        for (int u = 0; u < 4; ++u) if (u < sz){
            V[u + sz] = mul2(V[u], sb);
            V[u]      = mul2(V[u], cb);
        }
    }

    const u64 PM   = pk2( 1.0f, -1.0f);
    const u64 NPM  = pk2(-1.0f,  1.0f);
    const u64 NEG1 = pk2(-1.0f, -1.0f);
    const u64 POS1 = pk2( 1.0f,  1.0f);

    float* S = smx[warp];
    const int wbase = lane * 17;
    const int rbase = (lane & 16) * 17 + (lane & 15);

    // ---- WHT: 4 reg stages, transpose, 4 reg stages, 1 shfl stage (bit 8) ----
#pragma unroll
    for (int p = 0; p < 8; ++p) V[p] = fma2(PM, V[p], swp2(V[p]));   // bit0
#pragma unroll
    for (int k = 0; k < 3; ++k){                                     // bits 1..3
        const int m = 1 << k;
#pragma unroll
        for (int p = 0; p < 8; ++p) if (!(p & m)){
            const u64 A = V[p], B = V[p | m];
            V[p]     = add2(A, B);
            V[p | m] = fma2(NEG1, B, A);
        }
    }
    xpose(V, S, wbase, rbase);          // now reg bits = old j7..4 (layout B)
#pragma unroll
    for (int p = 0; p < 8; ++p) V[p] = fma2(PM, V[p], swp2(V[p]));
#pragma unroll
    for (int k = 0; k < 3; ++k){
        const int m = 1 << k;
#pragma unroll
        for (int p = 0; p < 8; ++p) if (!(p & m)){
            const u64 A = V[p], B = V[p | m];
            V[p]     = add2(A, B);
            V[p | m] = fma2(NEG1, B, A);
        }
    }
    {   // bit 8 (lane bit 4)
        const u64 sg8 = (lane & 16) ? NEG1 : POS1;
#pragma unroll
        for (int p = 0; p < 8; ++p){
            const u64 oth = __shfl_xor_sync(0xffffffffu, V[p], 16);
            V[p] = fma2(sg8, V[p], oth);
        }
    }

    // ---- scatter through CNOT-ring perm (skewed addressing, conflict-free reads) ----
    __syncwarp();
    const int pbase = permref(((lane & 16) << 4) | (lane & 15));
#pragma unroll
    for (int p = 0; p < 8; ++p){
        const int id0 = pbase ^ permref((2*p)     << 4);
        const int id1 = pbase ^ permref((2*p + 1) << 4);
        S[id0 + (id0 >> 5)] = lo2(V[p]);
        S[id1 + (id1 >> 5)] = hi2(V[p]);
    }
    __syncwarp();
    u64 Bse[8];                          // base state, layout A
#pragma unroll
    for (int p = 0; p < 8; ++p){
        const int a0 = (lane << 4) | (2*p);
        const int a1 = a0 | 1;
        Bse[p] = pk2(S[a0 + (a0 >> 5)], S[a1 + (a1 >> 5)]);
    }

    // ---- channels: y = (x) Rot(-phi) stages (tangent form), squares with sign ----
    const float tsgn  = (__popc(lane & 15) & 1) ? -1.0f : 1.0f;
    const int   obase = (b * OCH) * LOUT + t;
    const u64   FLIPH = 0x8000000000000000ULL;   // (t,t) -> (t,-t)
    const u64   FLIPB = 0x8000000080000000ULL;   // (t,t) -> (-t,-t)

    for (int o = 0; o < OCH; ++o){
        u64 Z[8];
#pragma unroll
        for (int p = 0; p < 8; ++p) Z[p] = Bse[p];

        // group1, layout A reg bits: bit0=qubit8(qi7); bits1..3=qubits7,6,5(qi6,5,4)
        {
            const u64 tp = gtt[o][7] ^ FLIPH;
#pragma unroll
            for (int p = 0; p < 8; ++p) Z[p] = fma2(tp, swp2(Z[p]), Z[p]);
        }
#pragma unroll
        for (int k = 0; k < 3; ++k){
            const int m  = 1 << k;
            const u64 tb  = gtt[o][6 - k];
            const u64 ntb = tb ^ FLIPB;
#pragma unroll
            for (int p = 0; p < 8; ++p) if (!(p & m)){
                const u64 A = Z[p], Bb = Z[p | m];
                Z[p]     = fma2(tb,  Bb, A);
                Z[p | m] = fma2(ntb, A,  Bb);
            }
        }

        xpose(Z, S, wbase, rbase);       // layout B: reg bits = j7..4

        // group2: bit0=qubit4(qi3); bits1..3=qubits3,2,1(qi2,1,0)
        {
            const u64 tp = gtt[o][3] ^ FLIPH;
#pragma unroll
            for (int p = 0; p < 8; ++p) Z[p] = fma2(tp, swp2(Z[p]), Z[p]);
        }
#pragma unroll
        for (int k = 0; k < 3; ++k){
            const int m  = 1 << k;
            const u64 tb  = gtt[o][2 - k];
            const u64 ntb = tb ^ FLIPB;
#pragma unroll
            for (int p = 0; p < 8; ++p) if (!(p & m)){
                const u64 A = Z[p], Bb = Z[p | m];
                Z[p]     = fma2(tb,  Bb, A);
                Z[p | m] = fma2(ntb, A,  Bb);
            }
        }

        // result = K * sum_j (-1)^popc(j&255) y_j^2 ; here sign = par(r)^par(lane&15)
        u64 acc2 = 0;                    // (0.0f, 0.0f)
#pragma unroll
        for (int p = 0; p < 8; ++p){
            const u64 sp = (__popc(p) & 1) ? NPM : PM;
            acc2 = fma2(mul2(Z[p], sp), Z[p], acc2);
        }
        float acc = (lo2(acc2) + hi2(acc2)) * tsgn * gK[o];
#pragma unroll
        for (int off = 16; off; off >>= 1)
            acc += __shfl_xor_sync(0xffffffffu, acc, off);
        if (lane == 0) out[obase + o * LOUT] = acc;
    }
}

extern "C" void kernel_launch(void* const* d_in, const int* in_sizes, int n_in,
                              void* d_out, int out_size)
{
    const float* x_ptr  = nullptr;
    const float* th_ptr = nullptr;
    for (int i = 0; i < n_in; ++i){
        if (in_sizes[i] == BATCH * C_CH * LEN) x_ptr  = (const float*)d_in[i];
        else if (in_sizes[i] == OCH * N_Q)     th_ptr = (const float*)d_in[i];
    }
    if (!x_ptr)  x_ptr  = (const float*)d_in[0];
    if (!th_ptr) th_ptr = (const float*)d_in[n_in - 1];

    qconv_kernel<<<LOUT, 256>>>(x_ptr, th_ptr, (float*)d_out);
}

// round 3
// speedup vs baseline: 1.8429x; 1.0831x over previous
#include <cuda_runtime.h>

typedef unsigned long long u64;

#define N_Q   9
#define C_CH  3
#define LEN   2048
#define LOUT  2046
#define BATCH 8
#define OCH   8
#define WPB   8
#define XTAB_N (BATCH * C_CH * LEN)

// ---------- packed f32x2 helpers (ptxas won't auto-fuse these) ----------
__device__ __forceinline__ u64 pk2(float lo, float hi){
    u64 r; asm("mov.b64 %0, {%1, %2};" : "=l"(r) : "f"(lo), "f"(hi)); return r;
}
__device__ __forceinline__ float lo2(u64 v){
    float a; asm("{.reg .b32 h_; mov.b64 {%0, h_}, %1;}" : "=f"(a) : "l"(v)); return a;
}
__device__ __forceinline__ float hi2(u64 v){
    float a; asm("{.reg .b32 l_; mov.b64 {l_, %0}, %1;}" : "=f"(a) : "l"(v)); return a;
}
__device__ __forceinline__ u64 fma2(u64 a, u64 b, u64 c){
    u64 d; asm("fma.rn.f32x2 %0, %1, %2, %3;" : "=l"(d) : "l"(a), "l"(b), "l"(c)); return d;
}
__device__ __forceinline__ u64 mul2(u64 a, u64 b){
    u64 d; asm("mul.rn.f32x2 %0, %1, %2;" : "=l"(d) : "l"(a), "l"(b)); return d;
}
__device__ __forceinline__ u64 add2(u64 a, u64 b){
    u64 d; asm("add.rn.f32x2 %0, %1, %2;" : "=l"(d) : "l"(a), "l"(b)); return d;
}
__device__ __forceinline__ u64 swp2(u64 v){
    u64 r; asm("{.reg .b32 a_, b_; mov.b64 {a_, b_}, %1; mov.b64 %0, {b_, a_};}"
               : "=l"(r) : "l"(v)); return r;
}

// ---------- precomputed tables ----------
__device__ float2 g_xtab[XTAB_N];     // (cos(x/2), sin(x/2)) per sample
__device__ u64    g_gtt[OCH][8];      // (tan phi, tan phi) packs, qubits 1..8
__device__ float  g_gK[OCH];          // (prod cos phi)^2 per channel

__global__ void setup_kernel(const float* __restrict__ x,
                             const float* __restrict__ theta)
{
    const int idx = blockIdx.x * blockDim.x + threadIdx.x;
    if (idx < XTAB_N){
        float s, c; sincosf(0.5f * x[idx], &s, &c);
        g_xtab[idx] = make_float2(c, s);
    }
    if (idx < OCH){
        float k = 1.0f;
#pragma unroll
        for (int q = 0; q < 8; ++q){
            const float th  = theta[idx * N_Q + q + 1];   // qubit 0 drops out
            const float phi = 0.78539816339744830962f - 0.5f * th;
            float s, c; sincosf(phi, &s, &c);
            const float tt = s / c;
            g_gtt[idx][q] = pk2(tt, tt);
            k *= c * c;
        }
        g_gK[idx] = k;
    }
}

// CNOT-ring permutation (replicates reference idx construction; linear over GF(2))
__device__ __forceinline__ int permref(int id){
#pragma unroll
    for (int c = 0; c < N_Q - 1; ++c){
        const int bit = (id >> (N_Q - 1 - c)) & 1;
        id ^= bit << (N_Q - 2 - c);
    }
    id ^= (id & 1) << (N_Q - 1);
    return id;
}

// Transpose within a warp: swap index bits 7..4 <-> 3..0 (bit 8 = lane bit 4 fixed).
__device__ __forceinline__ void xpose(u64* V, float* S, int wbase, int rbase){
    __syncwarp();
#pragma unroll
    for (int p = 0; p < 8; ++p){
        S[wbase + 2*p]     = lo2(V[p]);
        S[wbase + 2*p + 1] = hi2(V[p]);
    }
    __syncwarp();
#pragma unroll
    for (int p = 0; p < 8; ++p)
        V[p] = pk2(S[rbase + 17*(2*p)], S[rbase + 17*(2*p + 1)]);
}

__global__ __launch_bounds__(256)
void qconv_kernel(float* __restrict__ out)
{
    __shared__ float smx[WPB][544];      // per-warp transpose / perm buffer
    __shared__ u64   gtt[OCH][8];
    __shared__ float gK[OCH];

    const int tid  = threadIdx.x;
    const int warp = tid >> 5;
    const int lane = tid & 31;
    const int t    = blockIdx.x;         // window position
    const int b    = warp;               // batch

    if (tid < OCH * 8) gtt[tid >> 3][tid & 7] = g_gtt[tid >> 3][tid & 7];
    if (tid < OCH)     gK[tid] = g_gK[tid];
    __syncthreads();

    // ---- window angle cos/sin from table (broadcast loads) ----
    float cx[N_Q], sx[N_Q];
#pragma unroll
    for (int i = 0; i < N_Q; ++i){
        const float2 cs = g_xtab[(b * C_CH + i / 3) * LEN + t + (i % 3)];
        cx[i] = cs.x; sx[i] = cs.y;
    }

    // ---- product state, layout A: j = lane<<4 | r ; qubit q <-> bit 8-q ----
    float lf = 0.044194173824159220275f;     // 1/sqrt(512) folded in
#pragma unroll
    for (int i = 0; i < 5; ++i)
        lf *= ((lane >> (4 - i)) & 1) ? sx[i] : cx[i];

    u64 V[8];
    V[0] = mul2(pk2(lf, lf), pk2(cx[8], sx[8]));
#pragma unroll
    for (int bp = 1; bp < 4; ++bp){
        const int qi = 8 - bp;
        const u64 cb = pk2(cx[qi], cx[qi]);
        const u64 sb = pk2(sx[qi], sx[qi]);
        const int sz = 1 << (bp - 1);
#pragma unroll
        for (int u = 0; u < 4; ++u) if (u < sz){
            V[u + sz] = mul2(V[u], sb);
            V[u]      = mul2(V[u], cb);
        }
    }

    const u64 PM   = pk2( 1.0f, -1.0f);
    const u64 NEG1 = pk2(-1.0f, -1.0f);
    const u64 POS1 = pk2( 1.0f,  1.0f);

    float* S = smx[warp];
    const int wbase = lane * 17;
    const int rbase = (lane & 16) * 17 + (lane & 15);

    // ---- WHT ----
#pragma unroll
    for (int p = 0; p < 8; ++p) V[p] = fma2(PM, V[p], swp2(V[p]));
#pragma unroll
    for (int k = 0; k < 3; ++k){
        const int m = 1 << k;
#pragma unroll
        for (int p = 0; p < 8; ++p) if (!(p & m)){
            const u64 A = V[p], B = V[p | m];
            V[p]     = add2(A, B);
            V[p | m] = fma2(NEG1, B, A);
        }
    }
    xpose(V, S, wbase, rbase);
#pragma unroll
    for (int p = 0; p < 8; ++p) V[p] = fma2(PM, V[p], swp2(V[p]));
#pragma unroll
    for (int k = 0; k < 3; ++k){
        const int m = 1 << k;
#pragma unroll
        for (int p = 0; p < 8; ++p) if (!(p & m)){
            const u64 A = V[p], B = V[p | m];
            V[p]     = add2(A, B);
            V[p | m] = fma2(NEG1, B, A);
        }
    }
    {
        const u64 sg8 = (lane & 16) ? NEG1 : POS1;
#pragma unroll
        for (int p = 0; p < 8; ++p){
            const u64 oth = __shfl_xor_sync(0xffffffffu, V[p], 16);
            V[p] = fma2(sg8, V[p], oth);
        }
    }

    // ---- scatter through CNOT-ring perm ----
    __syncwarp();
    const int pbase = permref(((lane & 16) << 4) | (lane & 15));
#pragma unroll
    for (int p = 0; p < 8; ++p){
        const int id0 = pbase ^ permref((2*p)     << 4);
        const int id1 = pbase ^ permref((2*p + 1) << 4);
        S[id0 + (id0 >> 5)] = lo2(V[p]);
        S[id1 + (id1 >> 5)] = hi2(V[p]);
    }
    __syncwarp();
    u64 Bse[8];
#pragma unroll
    for (int p = 0; p < 8; ++p){
        const int a0 = (lane << 4) | (2*p);
        const int a1 = a0 | 1;
        Bse[p] = pk2(S[a0 + (a0 >> 5)], S[a1 + (a1 >> 5)]);
    }

    // ---- channels ----
    const float tsgn  = (__popc(lane & 15) & 1) ? -1.0f : 1.0f;
    const int   obase = (b * OCH) * LOUT + t;
    const u64   FLIPH = 0x8000000000000000ULL;
    const u64   FLIPB = 0x8000000080000000ULL;

    for (int o = 0; o < OCH; ++o){
        u64 Z[8];
#pragma unroll
        for (int p = 0; p < 8; ++p) Z[p] = Bse[p];

        {   // group1 in-pack stage (qubit 8)
            const u64 tp = gtt[o][7] ^ FLIPH;
#pragma unroll
            for (int p = 0; p < 8; ++p) Z[p] = fma2(tp, swp2(Z[p]), Z[p]);
        }
#pragma unroll
        for (int k = 0; k < 3; ++k){
            const int m  = 1 << k;
            const u64 tb  = gtt[o][6 - k];
            const u64 ntb = tb ^ FLIPB;
#pragma unroll
            for (int p = 0; p < 8; ++p) if (!(p & m)){
                const u64 A = Z[p], Bb = Z[p | m];
                Z[p]     = fma2(tb,  Bb, A);
                Z[p | m] = fma2(ntb, A,  Bb);
            }
        }

        xpose(Z, S, wbase, rbase);

        {   // group2 in-pack stage (qubit 4)
            const u64 tp = gtt[o][3] ^ FLIPH;
#pragma unroll
            for (int p = 0; p < 8; ++p) Z[p] = fma2(tp, swp2(Z[p]), Z[p]);
        }
#pragma unroll
        for (int k = 0; k < 3; ++k){
            const int m  = 1 << k;
            const u64 tb  = gtt[o][2 - k];
            const u64 ntb = tb ^ FLIPB;
#pragma unroll
            for (int p = 0; p < 8; ++p) if (!(p & m)){
                const u64 A = Z[p], Bb = Z[p | m];
                Z[p]     = fma2(tb,  Bb, A);
                Z[p | m] = fma2(ntb, A,  Bb);
            }
        }

        // signed squares, parity-split:
        // sign(j) = tsgn * (-1)^popc(p) * (-1)^half
        u64 accE = 0, accO = 0;       // (0.0f,0.0f) bit pattern
        accE = fma2(Z[0], Z[0], accE);
        accO = fma2(Z[1], Z[1], accO);
        accO = fma2(Z[2], Z[2], accO);
        accE = fma2(Z[3], Z[3], accE);
        accO = fma2(Z[4], Z[4], accO);
        accE = fma2(Z[5], Z[5], accE);
        accE = fma2(Z[6], Z[6], accE);
        accO = fma2(Z[7], Z[7], accO);

        const float kk = tsgn * gK[o];
        float acc = ((lo2(accE) - hi2(accE)) - (lo2(accO) - hi2(accO))) * kk;
#pragma unroll
        for (int off = 16; off; off >>= 1)
            acc += __shfl_xor_sync(0xffffffffu, acc, off);
        if (lane == 0) out[obase + o * LOUT] = acc;
    }
}

extern "C" void kernel_launch(void* const* d_in, const int* in_sizes, int n_in,
                              void* d_out, int out_size)
{
    const float* x_ptr  = nullptr;
    const float* th_ptr = nullptr;
    for (int i = 0; i < n_in; ++i){
        if (in_sizes[i] == BATCH * C_CH * LEN) x_ptr  = (const float*)d_in[i];
        else if (in_sizes[i] == OCH * N_Q)     th_ptr = (const float*)d_in[i];
    }
    if (!x_ptr)  x_ptr  = (const float*)d_in[0];
    if (!th_ptr) th_ptr = (const float*)d_in[n_in - 1];

    setup_kernel<<<(XTAB_N + 255) / 256, 256>>>(x_ptr, th_ptr);
    qconv_kernel<<<LOUT, 256>>>((float*)d_out);
}

// round 5
// speedup vs baseline: 2.0378x; 1.1058x over previous
#include <cuda_runtime.h>

typedef unsigned long long u64;

#define N_Q   9
#define C_CH  3
#define LEN   2048
#define LOUT  2046
#define BATCH 8
#define OCH   8
#define WPB   8
#define XTAB_N (BATCH * C_CH * LEN)
#define HSTR  560                    // hi-bit stride: mod32=16 (bank shift), >=544 (no alias)
#define SWARP (2 * HSTR + 8 * 36)    // 1120 xpose/perm region + 288 partials

// ---------- packed f32x2 helpers ----------
__device__ __forceinline__ u64 pk2(float lo, float hi){
    u64 r; asm("mov.b64 %0, {%1, %2};" : "=l"(r) : "f"(lo), "f"(hi)); return r;
}
__device__ __forceinline__ float lo2(u64 v){
    float a; asm("{.reg .b32 h_; mov.b64 {%0, h_}, %1;}" : "=f"(a) : "l"(v)); return a;
}
__device__ __forceinline__ float hi2(u64 v){
    float a; asm("{.reg .b32 l_; mov.b64 {l_, %0}, %1;}" : "=f"(a) : "l"(v)); return a;
}
__device__ __forceinline__ u64 fma2(u64 a, u64 b, u64 c){
    u64 d; asm("fma.rn.f32x2 %0, %1, %2, %3;" : "=l"(d) : "l"(a), "l"(b), "l"(c)); return d;
}
__device__ __forceinline__ u64 mul2(u64 a, u64 b){
    u64 d; asm("mul.rn.f32x2 %0, %1, %2;" : "=l"(d) : "l"(a), "l"(b)); return d;
}
__device__ __forceinline__ u64 add2(u64 a, u64 b){
    u64 d; asm("add.rn.f32x2 %0, %1, %2;" : "=l"(d) : "l"(a), "l"(b)); return d;
}

// ---------- precomputed tables ----------
__device__ float2 g_xtab[XTAB_N];     // (cos(x/2), sin(x/2)) per sample
__device__ u64    g_gtt[OCH][8];      // (tan phi, tan phi) packs, qubits 1..8
__device__ float  g_gK[OCH];          // (prod cos phi)^2 per channel

__global__ void setup_kernel(const float* __restrict__ x,
                             const float* __restrict__ theta)
{
    const int idx = blockIdx.x * blockDim.x + threadIdx.x;
    if (idx < XTAB_N){
        float s, c; sincosf(0.5f * x[idx], &s, &c);
        g_xtab[idx] = make_float2(c, s);
    }
    if (idx < OCH){
        float k = 1.0f;
#pragma unroll
        for (int q = 0; q < 8; ++q){
            const float th  = theta[idx * N_Q + q + 1];   // qubit 0 drops out
            const float phi = 0.78539816339744830962f - 0.5f * th;
            float s, c; sincosf(phi, &s, &c);
            const float tt = s / c;
            g_gtt[idx][q] = pk2(tt, tt);
            k *= c * c;
        }
        g_gK[idx] = k;
    }
}

// CNOT-ring permutation (replicates reference idx construction; linear over GF(2))
__device__ __forceinline__ int permref(int id){
#pragma unroll
    for (int c = 0; c < N_Q - 1; ++c){
        const int bit = (id >> (N_Q - 1 - c)) & 1;
        id ^= bit << (N_Q - 2 - c);
    }
    id ^= (id & 1) << (N_Q - 1);
    return id;
}

// Injective smem map for 9-bit index j = (hi | mid4 | low4):
//   addr = low + 34*mid + 560*hi.
// hi blocks [0,525] and [560,1085] are disjoint; 560%32==16 keeps banks spread.
__device__ __forceinline__ int sm_addr(int j){
    return (j & 15) + 34 * ((j >> 4) & 15) + HSTR * (j >> 8);
}

__global__ __launch_bounds__(256)
void qconv_kernel(float* __restrict__ out)
{
    __shared__ __align__(16) float smx[WPB][SWARP];
    __shared__ u64   gtt[OCH][8];
    __shared__ float gK[OCH];

    const int tid  = threadIdx.x;
    const int warp = tid >> 5;
    const int lane = tid & 31;
    const int t    = blockIdx.x;         // window position
    const int b    = warp;               // batch

    if (tid < OCH * 8) gtt[tid >> 3][tid & 7] = g_gtt[tid >> 3][tid & 7];
    if (tid < OCH)     gK[tid] = g_gK[tid];
    __syncthreads();

    float* S  = smx[warp];
    float* Sp = smx[warp] + 2 * HSTR;    // partial-sum region (disjoint)
    const int l4  = lane >> 4;
    const int llo = lane & 15;
    const int wb  = llo + HSTR * l4;             // xpose write base (+34*r)
    const int rb  = 34 * llo + HSTR * l4;        // xpose/Bse read base (even)

    // ---- window angle cos/sin from table ----
    float cx[N_Q], sx[N_Q];
#pragma unroll
    for (int i = 0; i < N_Q; ++i){
        const float2 cs = g_xtab[(b * C_CH + i / 3) * LEN + t + (i % 3)];
        cx[i] = cs.x; sx[i] = cs.y;
    }

    // ---- product state, layout A: j = lane<<4 | r ; qubit q <-> bit 8-q ----
    float lf = 0.044194173824159220275f;     // 1/sqrt(512) folded in
#pragma unroll
    for (int i = 0; i < 5; ++i)
        lf *= ((lane >> (4 - i)) & 1) ? sx[i] : cx[i];

    u64 V[8];
    V[0] = mul2(pk2(lf, lf), pk2(cx[8], sx[8]));   // pack bit = qubit 8
#pragma unroll
    for (int bp = 1; bp < 4; ++bp){                // reg bits 1..3 = qubits 7,6,5
        const int qi = 8 - bp;
        const u64 cb = pk2(cx[qi], cx[qi]);
        const u64 sb = pk2(sx[qi], sx[qi]);
        const int sz = 1 << (bp - 1);
#pragma unroll
        for (int u = 0; u < 4; ++u) if (u < sz){
            V[u + sz] = mul2(V[u], sb);
            V[u]      = mul2(V[u], cb);
        }
    }

    const u64 NEG1 = pk2(-1.0f, -1.0f);
    const u64 POS1 = pk2( 1.0f,  1.0f);
    const u64 FLIPB = 0x8000000080000000ULL;

    // ---- WHT: pack stage (scalar halves), 3 reg stages ----
#pragma unroll
    for (int p = 0; p < 8; ++p){
        const float a = lo2(V[p]), c = hi2(V[p]);
        V[p] = pk2(a + c, a - c);
    }
#pragma unroll
    for (int k = 0; k < 3; ++k){
        const int m = 1 << k;
#pragma unroll
        for (int p = 0; p < 8; ++p) if (!(p & m)){
            const u64 A = V[p], B = V[p | m];
            V[p]     = add2(A, B);
            V[p | m] = fma2(NEG1, B, A);
        }
    }
    // transpose (scattered STS.32, contiguous LDS.64) + next WHT pack-stage fused
    __syncwarp();
#pragma unroll
    for (int p = 0; p < 8; ++p){
        S[wb + 34 * (2 * p)]     = lo2(V[p]);
        S[wb + 34 * (2 * p + 1)] = hi2(V[p]);
    }
    __syncwarp();
    {
        const float2* R = (const float2*)(S + rb);
#pragma unroll
        for (int p = 0; p < 8; ++p){
            const float2 w = R[p];
            V[p] = pk2(w.x + w.y, w.x - w.y);      // WHT stage on new pack bit
        }
    }
#pragma unroll
    for (int k = 0; k < 3; ++k){
        const int m = 1 << k;
#pragma unroll
        for (int p = 0; p < 8; ++p) if (!(p & m)){
            const u64 A = V[p], B = V[p | m];
            V[p]     = add2(A, B);
            V[p | m] = fma2(NEG1, B, A);
        }
    }
    {   // WHT stage on bit 8 (lane bit 4)
        const u64 sg8 = (lane & 16) ? NEG1 : POS1;
#pragma unroll
        for (int p = 0; p < 8; ++p){
            const u64 oth = __shfl_xor_sync(0xffffffffu, V[p], 16);
            V[p] = fma2(sg8, V[p], oth);
        }
    }

    // ---- scatter through CNOT-ring perm; read back contiguous (layout A) ----
    // In layout B, (lane, r'=2p|2p+1) holds element j: j[3:0]=llo, j[7:4]=r', j[8]=l4.
    __syncwarp();
    const int pbase = permref(((lane & 16) << 4) | (lane & 15));
#pragma unroll
    for (int p = 0; p < 8; ++p){
        const int id0 = pbase ^ permref((2 * p)     << 4);
        const int id1 = pbase ^ permref((2 * p + 1) << 4);
        S[sm_addr(id0)] = lo2(V[p]);
        S[sm_addr(id1)] = hi2(V[p]);
    }
    __syncwarp();
    u64 Bse[8];
    {
        const float2* R = (const float2*)(S + rb);
#pragma unroll
        for (int p = 0; p < 8; ++p){
            const float2 w = R[p];
            Bse[p] = pk2(w.x, w.y);
        }
    }

    // ---- channels ----
    const float tsgn = (__popc(lane & 15) & 1) ? -1.0f : 1.0f;

    for (int o = 0; o < OCH; ++o){
        u64 Z[8];
        {   // group1 pack-stage (qubit 8), scalar on halves of Bse
            const float t7 = lo2(gtt[o][7]);
#pragma unroll
            for (int p = 0; p < 8; ++p){
                const float bl = lo2(Bse[p]), bh = hi2(Bse[p]);
                Z[p] = pk2(fmaf(t7, bh, bl), fmaf(-t7, bl, bh));
            }
        }
#pragma unroll
        for (int k = 0; k < 3; ++k){             // qubits 7,6,5
            const int m  = 1 << k;
            const u64 tb  = gtt[o][6 - k];
            const u64 ntb = tb ^ FLIPB;
#pragma unroll
            for (int p = 0; p < 8; ++p) if (!(p & m)){
                const u64 A = Z[p], Bb = Z[p | m];
                Z[p]     = fma2(tb,  Bb, A);
                Z[p | m] = fma2(ntb, A,  Bb);
            }
        }

        // transpose + fused qubit-4 rotation on the 64-bit read
        __syncwarp();
#pragma unroll
        for (int p = 0; p < 8; ++p){
            S[wb + 34 * (2 * p)]     = lo2(Z[p]);
            S[wb + 34 * (2 * p + 1)] = hi2(Z[p]);
        }
        __syncwarp();
        {
            const float t3 = lo2(gtt[o][3]);
            const float2* R = (const float2*)(S + rb);
#pragma unroll
            for (int p = 0; p < 8; ++p){
                const float2 w = R[p];
                Z[p] = pk2(fmaf(t3, w.y, w.x), fmaf(-t3, w.x, w.y));
            }
        }
#pragma unroll
        for (int k = 0; k < 3; ++k){             // qubits 3,2,1
            const int m  = 1 << k;
            const u64 tb  = gtt[o][2 - k];
            const u64 ntb = tb ^ FLIPB;
#pragma unroll
            for (int p = 0; p < 8; ++p) if (!(p & m)){
                const u64 A = Z[p], Bb = Z[p | m];
                Z[p]     = fma2(tb,  Bb, A);
                Z[p | m] = fma2(ntb, A,  Bb);
            }
        }

        // signed squares, parity-split over popc(p)
        u64 accE = 0, accO = 0;
        accE = fma2(Z[0], Z[0], accE);
        accO = fma2(Z[1], Z[1], accO);
        accO = fma2(Z[2], Z[2], accO);
        accE = fma2(Z[3], Z[3], accE);
        accO = fma2(Z[4], Z[4], accO);
        accE = fma2(Z[5], Z[5], accE);
        accE = fma2(Z[6], Z[6], accE);
        accO = fma2(Z[7], Z[7], accO);

        const float raw = (lo2(accE) - hi2(accE)) - (lo2(accO) - hi2(accO));
        Sp[o * 36 + ((lane + o) & 31)] = raw * tsgn;   // conflict-free swizzle
    }

    // ---- cooperative 8-channel reduction: 8 LDS + 2 SHFL per thread ----
    __syncwarp();
    {
        const int ch = lane >> 2;
        const int i  = lane & 3;
        float tot = 0.0f;
#pragma unroll
        for (int m = 0; m < 8; ++m)
            tot += Sp[ch * 36 + ((8 * i + m + ch) & 31)];
        tot += __shfl_xor_sync(0xffffffffu, tot, 1);
        tot += __shfl_xor_sync(0xffffffffu, tot, 2);
        if (i == 0)
            out[(b * OCH + ch) * LOUT + t] = tot * gK[ch];
    }
}

extern "C" void kernel_launch(void* const* d_in, const int* in_sizes, int n_in,
                              void* d_out, int out_size)
{
    const float* x_ptr  = nullptr;
    const float* th_ptr = nullptr;
    for (int i = 0; i < n_in; ++i){
        if (in_sizes[i] == BATCH * C_CH * LEN) x_ptr  = (const float*)d_in[i];
        else if (in_sizes[i] == OCH * N_Q)     th_ptr = (const float*)d_in[i];
    }
    if (!x_ptr)  x_ptr  = (const float*)d_in[0];
    if (!th_ptr) th_ptr = (const float*)d_in[n_in - 1];

    setup_kernel<<<(XTAB_N + 255) / 256, 256>>>(x_ptr, th_ptr);
    qconv_kernel<<<LOUT, 256>>>((float*)d_out);
}

// round 6
// speedup vs baseline: 2.2594x; 1.1087x over previous
#include <cuda_runtime.h>

typedef unsigned long long u64;

#define N_Q   9
#define C_CH  3
#define LEN   2048
#define LOUT  2046
#define BATCH 8
#define OCH   8
#define WPB   8
#define HSTR  560                    // hi-bit stride: mod32=16 (bank shift), >=544 (no alias)
#define SWARP (2 * HSTR + 8 * 36)    // 1120 scatter/xpose region + 288 partials

// ---------- packed f32x2 helpers ----------
__device__ __forceinline__ u64 pk2(float lo, float hi){
    u64 r; asm("mov.b64 %0, {%1, %2};" : "=l"(r) : "f"(lo), "f"(hi)); return r;
}
__device__ __forceinline__ float lo2(u64 v){
    float a; asm("{.reg .b32 h_; mov.b64 {%0, h_}, %1;}" : "=f"(a) : "l"(v)); return a;
}
__device__ __forceinline__ float hi2(u64 v){
    float a; asm("{.reg .b32 l_; mov.b64 {l_, %0}, %1;}" : "=f"(a) : "l"(v)); return a;
}
__device__ __forceinline__ u64 fma2(u64 a, u64 b, u64 c){
    u64 d; asm("fma.rn.f32x2 %0, %1, %2, %3;" : "=l"(d) : "l"(a), "l"(b), "l"(c)); return d;
}
__device__ __forceinline__ u64 mul2(u64 a, u64 b){
    u64 d; asm("mul.rn.f32x2 %0, %1, %2;" : "=l"(d) : "l"(a), "l"(b)); return d;
}

// CNOT-ring permutation (replicates reference idx construction; linear over GF(2))
__device__ __forceinline__ int permref(int id){
#pragma unroll
    for (int c = 0; c < N_Q - 1; ++c){
        const int bit = (id >> (N_Q - 1 - c)) & 1;
        id ^= bit << (N_Q - 2 - c);
    }
    id ^= (id & 1) << (N_Q - 1);
    return id;
}

// Injective smem map for 9-bit index j = (hi | mid4 | low4):
//   addr = low + 34*mid + 560*hi.
__device__ __forceinline__ int sm_addr(int j){
    return (j & 15) + 34 * ((j >> 4) & 15) + HSTR * (j >> 8);
}

__global__ __launch_bounds__(256)
void qconv_kernel(const float* __restrict__ x,
                  const float* __restrict__ theta,
                  float* __restrict__ out)
{
    __shared__ __align__(16) float smx[WPB][SWARP];
    __shared__ u64   gtt[OCH][8];     // (tan phi, tan phi), qubits 1..8
    __shared__ float gK[OCH];         // (prod cos phi)^2 per channel
    __shared__ float gc2[OCH * 8];

    const int tid  = threadIdx.x;
    const int warp = tid >> 5;
    const int lane = tid & 31;
    const int t    = blockIdx.x;         // window position
    const int b    = warp;               // batch

    // ---- in-block gate prep (replaces setup kernel): phi = pi/4 - theta/2 ----
    if (tid < OCH * 8){
        const int o = tid >> 3, qi = tid & 7;          // qubit = qi+1 (qubit 0 drops out)
        const float th  = theta[o * N_Q + qi + 1];
        const float phi = 0.78539816339744830962f - 0.5f * th;
        float s, c; sincosf(phi, &s, &c);
        const float tt = __fdividef(s, c);
        gtt[o][qi] = pk2(tt, tt);
        gc2[tid]   = c * c;
    }
    __syncthreads();
    if (tid < OCH){
        float k = 1.0f;
#pragma unroll
        for (int q = 0; q < 8; ++q) k *= gc2[tid * 8 + q];
        gK[tid] = k;
    }
    __syncthreads();

    float* S  = smx[warp];
    float* Sp = smx[warp] + 2 * HSTR;    // partial-sum region (disjoint)
    const int l4  = lane >> 4;
    const int llo = lane & 15;
    const int wb  = llo + HSTR * l4;             // xpose write base (+34*r)
    const int rb  = 34 * llo + HSTR * l4;        // xpose/Bse read base (even)

    // ---- WHT-domain per-qubit factors: H[c,s] ∝ (c+s, c-s) ----
    float av[N_Q], bv[N_Q];
#pragma unroll
    for (int i = 0; i < N_Q; ++i){
        const float xv = x[(b * C_CH + i / 3) * LEN + t + (i % 3)];
        float s, c; __sincosf(0.5f * xv, &s, &c);
        av[i] = c + s;
        bv[i] = c - s;
    }

    // ---- build WHT(state) DIRECTLY as a product state, in layout B:
    //   j[3:0]=llo  -> qubits 8,7,6,5 (bit k <-> qubit 8-k)
    //   j[4]  =pack -> qubit 4
    //   j[7:5]=p    -> qubits 3,2,1
    //   j[8]  =l4   -> qubit 0
    // 1/sqrt(512) of E folded into lf (WHT here is the unnormalized one).
    float lf = 0.044194173824159220275f;
    lf *= (lane & 16) ? bv[0] : av[0];
    lf *= (llo & 1)   ? bv[8] : av[8];
    lf *= (llo & 2)   ? bv[7] : av[7];
    lf *= (llo & 4)   ? bv[6] : av[6];
    lf *= (llo & 8)   ? bv[5] : av[5];

    u64 V[8];
    V[0] = mul2(pk2(lf, lf), pk2(av[4], bv[4]));   // pack bit = qubit 4
#pragma unroll
    for (int bp = 0; bp < 3; ++bp){                // p bits 0,1,2 = qubits 3,2,1
        const int q  = 3 - bp;
        const u64 ab = pk2(av[q], av[q]);
        const u64 bb = pk2(bv[q], bv[q]);
        const int sz = 1 << bp;
#pragma unroll
        for (int u = 0; u < 4; ++u) if (u < sz){
            V[u + sz] = mul2(V[u], bb);
            V[u]      = mul2(V[u], ab);
        }
    }

    const u64 FLIPB = 0x8000000080000000ULL;

    // ---- scatter through CNOT-ring perm; read back contiguous (layout A) ----
    const int pbase = permref(((lane & 16) << 4) | (lane & 15));
#pragma unroll
    for (int p = 0; p < 8; ++p){
        const int id0 = pbase ^ permref((2 * p)     << 4);
        const int id1 = pbase ^ permref((2 * p + 1) << 4);
        S[sm_addr(id0)] = lo2(V[p]);
        S[sm_addr(id1)] = hi2(V[p]);
    }
    __syncwarp();
    u64 Bse[8];
    {
        const float2* R = (const float2*)(S + rb);
#pragma unroll
        for (int p = 0; p < 8; ++p){
            const float2 w = R[p];
            Bse[p] = pk2(w.x, w.y);
        }
    }

    // ---- channels: layout A: j[8:4]=lane, pack=j0 (qubit 8), p bits=q7,6,5 ----
    const float tsgn = (__popc(lane & 15) & 1) ? -1.0f : 1.0f;

    for (int o = 0; o < OCH; ++o){
        u64 Z[8];
        {   // group1 pack-stage (qubit 8), scalar on halves of Bse
            const float t7 = lo2(gtt[o][7]);
#pragma unroll
            for (int p = 0; p < 8; ++p){
                const float bl = lo2(Bse[p]), bh = hi2(Bse[p]);
                Z[p] = pk2(fmaf(t7, bh, bl), fmaf(-t7, bl, bh));
            }
        }
#pragma unroll
        for (int k = 0; k < 3; ++k){             // qubits 7,6,5
            const int m  = 1 << k;
            const u64 tb  = gtt[o][6 - k];
            const u64 ntb = tb ^ FLIPB;
#pragma unroll
            for (int p = 0; p < 8; ++p) if (!(p & m)){
                const u64 A = Z[p], Bb = Z[p | m];
                Z[p]     = fma2(tb,  Bb, A);
                Z[p | m] = fma2(ntb, A,  Bb);
            }
        }

        // transpose + fused qubit-4 rotation on the 64-bit read
        __syncwarp();
#pragma unroll
        for (int p = 0; p < 8; ++p){
            S[wb + 34 * (2 * p)]     = lo2(Z[p]);
            S[wb + 34 * (2 * p + 1)] = hi2(Z[p]);
        }
        __syncwarp();
        {
            const float t3 = lo2(gtt[o][3]);
            const float2* R = (const float2*)(S + rb);
#pragma unroll
            for (int p = 0; p < 8; ++p){
                const float2 w = R[p];
                Z[p] = pk2(fmaf(t3, w.y, w.x), fmaf(-t3, w.x, w.y));
            }
        }
#pragma unroll
        for (int k = 0; k < 3; ++k){             // qubits 3,2,1
            const int m  = 1 << k;
            const u64 tb  = gtt[o][2 - k];
            const u64 ntb = tb ^ FLIPB;
#pragma unroll
            for (int p = 0; p < 8; ++p) if (!(p & m)){
                const u64 A = Z[p], Bb = Z[p | m];
                Z[p]     = fma2(tb,  Bb, A);
                Z[p | m] = fma2(ntb, A,  Bb);
            }
        }

        // signed squares, parity-split over popc(p)
        u64 accE = 0, accO = 0;
        accE = fma2(Z[0], Z[0], accE);
        accO = fma2(Z[1], Z[1], accO);
        accO = fma2(Z[2], Z[2], accO);
        accE = fma2(Z[3], Z[3], accE);
        accO = fma2(Z[4], Z[4], accO);
        accE = fma2(Z[5], Z[5], accE);
        accE = fma2(Z[6], Z[6], accE);
        accO = fma2(Z[7], Z[7], accO);

        const float raw = (lo2(accE) - hi2(accE)) - (lo2(accO) - hi2(accO));
        Sp[o * 36 + ((lane + o) & 31)] = raw * tsgn;   // conflict-free swizzle
    }

    // ---- cooperative 8-channel reduction: 8 LDS + 2 SHFL per thread ----
    __syncwarp();
    {
        const int ch = lane >> 2;
        const int i  = lane & 3;
        float tot = 0.0f;
#pragma unroll
        for (int m = 0; m < 8; ++m)
            tot += Sp[ch * 36 + ((8 * i + m + ch) & 31)];
        tot += __shfl_xor_sync(0xffffffffu, tot, 1);
        tot += __shfl_xor_sync(0xffffffffu, tot, 2);
        if (i == 0)
            out[(b * OCH + ch) * LOUT + t] = tot * gK[ch];
    }
}

extern "C" void kernel_launch(void* const* d_in, const int* in_sizes, int n_in,
                              void* d_out, int out_size)
{
    const float* x_ptr  = nullptr;
    const float* th_ptr = nullptr;
    for (int i = 0; i < n_in; ++i){
        if (in_sizes[i] == BATCH * C_CH * LEN) x_ptr  = (const float*)d_in[i];
        else if (in_sizes[i] == OCH * N_Q)     th_ptr = (const float*)d_in[i];
    }
    if (!x_ptr)  x_ptr  = (const float*)d_in[0];
    if (!th_ptr) th_ptr = (const float*)d_in[n_in - 1];

    qconv_kernel<<<LOUT, 256>>>(x_ptr, th_ptr, (float*)d_out);
}